// round 16
// baseline (speedup 1.0000x reference)
#include <cuda_runtime.h>
#include <cuda_fp16.h>
#include <math.h>

// ---------------------------------------------------------------------------
// GCNClassifier: 3x GCNConv (+leaky relu) + linear + log_softmax
// N = 100000, E = 1000000, dims 64 -> 80 -> 40 -> 50 -> 10
// Strategy: bucket CSR (CAP=64/node, no histogram/scan), fp16 storage for all
// gathered message buffers (x, Hs2, A2) with fp32 accumulation everywhere,
// thread-per-(node,group) gathers (no float atomics), register-tiled fused
// GEMMs with f32x2 FMAs. Layers 1 and 3 aggregate BEFORE their GEMM
// (Â(XW) = (ÂX)W); classifier head fused into gemm3. All kernels chained
// with Programmatic Dependent Launch.
// ---------------------------------------------------------------------------

#define N_NODES 100000
#define CAP     64
#define CAP_LOG 6
#define MAX_DIM 80

__device__ float  g_bufA[N_NODES * MAX_DIM];
__device__ float  g_bufB[N_NODES * MAX_DIM];
__device__ float  g_bufC[N_NODES * MAX_DIM];
__device__ float  g_dinv[N_NODES];
__device__ int    g_cur[N_NODES];
__device__ int    g_csrc[N_NODES * CAP];          // bucket array
__device__ __align__(16) __half g_hX[N_NODES * 64];   // x in fp16
__device__ __align__(16) __half g_hM[N_NODES * 40];   // Hs2 messages fp16
__device__ __align__(16) __half g_hA2[N_NODES * 40];  // A2 (layer-2 out) fp16

static inline int cdiv(int a, int b) { return (a + b - 1) / b; }

// ---------------------------------------------------------------------------
// PDL launch helper
// ---------------------------------------------------------------------------
template <typename... Args>
static void pdl_launch(void (*kern)(Args...), int grid, int block,
                       Args... args) {
    cudaLaunchConfig_t cfg = {};
    cfg.gridDim = dim3((unsigned)grid);
    cfg.blockDim = dim3((unsigned)block);
    cudaLaunchAttribute attr[1];
    attr[0].id = cudaLaunchAttributeProgrammaticStreamSerialization;
    attr[0].val.programmaticStreamSerializationAllowed = 1;
    cfg.attrs = attr;
    cfg.numAttrs = 1;
    cudaLaunchKernelEx(&cfg, kern, args...);
}

// ---------------------------------------------------------------------------
// half8 <-> float8 helpers
// ---------------------------------------------------------------------------
__device__ __forceinline__ void h8tof(uint4 v, float f[8]) {
    __half2 h;
    *reinterpret_cast<unsigned*>(&h) = v.x;
    float2 t = __half22float2(h); f[0] = t.x; f[1] = t.y;
    *reinterpret_cast<unsigned*>(&h) = v.y;
    t = __half22float2(h); f[2] = t.x; f[3] = t.y;
    *reinterpret_cast<unsigned*>(&h) = v.z;
    t = __half22float2(h); f[4] = t.x; f[5] = t.y;
    *reinterpret_cast<unsigned*>(&h) = v.w;
    t = __half22float2(h); f[6] = t.x; f[7] = t.y;
}

__device__ __forceinline__ uint4 ftoh8(const float f[8]) {
    uint4 o;
    __half2 h;
    h = __floats2half2_rn(f[0], f[1]); o.x = *reinterpret_cast<unsigned*>(&h);
    h = __floats2half2_rn(f[2], f[3]); o.y = *reinterpret_cast<unsigned*>(&h);
    h = __floats2half2_rn(f[4], f[5]); o.z = *reinterpret_cast<unsigned*>(&h);
    h = __floats2half2_rn(f[6], f[7]); o.w = *reinterpret_cast<unsigned*>(&h);
    return o;
}

// ---------------------------------------------------------------------------
// kernel 1: bucket cursor init + x -> fp16 conversion (fused). No PDL sync.
// n*8 threads: thread i converts x[8i..8i+7]; threads i<n also init cur.
// ---------------------------------------------------------------------------
__global__ void init_convert(const float4* __restrict__ X4,
                             uint4* __restrict__ XH, int* cur, int n) {
    int i = blockIdx.x * blockDim.x + threadIdx.x;
    if (i < n) cur[i] = i << CAP_LOG;
    if (i >= n * 8) return;
    float4 a = __ldg(&X4[2 * i]);
    float4 b = __ldg(&X4[2 * i + 1]);
    float f[8] = {a.x, a.y, a.z, a.w, b.x, b.y, b.z, b.w};
    XH[i] = ftoh8(f);
}

__global__ void csr_scatter(const int* __restrict__ src,
                            const int* __restrict__ dst,
                            int* cur, int* csrc, int E) {
    int e = blockIdx.x * blockDim.x + threadIdx.x;
    int s = 0, d = 0;
    if (e < E) {                          // harness inputs: safe pre-sync
        s = __ldg(&src[e]);
        d = __ldg(&dst[e]);
    }
    cudaGridDependencySynchronize();      // wait for init_convert (cur)
    if (e < E) {
        int pos = atomicAdd(&cur[d], 1);
        csrc[pos] = s;
    }
}

__global__ void dinv_fin(const int* __restrict__ cur, float* dinv, int n) {
    int i = blockIdx.x * blockDim.x + threadIdx.x;
    cudaGridDependencySynchronize();      // wait for csr_scatter
    if (i < n) {
        int deg = cur[i] - (i << CAP_LOG);
        dinv[i] = rsqrtf((float)deg + 1.0f);
    }
}

// ---------------------------------------------------------------------------
// layer-1 aggregate-first on fp16 x (dim 64 = 8 groups of 8 halves):
//   Z1[i] = dinv[i]*(sum_s dinv[s]*xh[s]) + dinv[i]^2 * xh[i]   (fp32 accum)
// ---------------------------------------------------------------------------
__global__ void agg_pre1_h(const uint4* __restrict__ XH,
                           const int* __restrict__ cur,
                           const int* __restrict__ csrc,
                           const float* __restrict__ dinv,
                           float4* __restrict__ Z, int n) {
    int idx = blockIdx.x * blockDim.x + threadIdx.x;
    int node = idx >> 3;
    int g = idx & 7;
    cudaGridDependencySynchronize();
    if (node >= n) return;
    int e = node << CAP_LOG;
    int e1 = __ldg(&cur[node]);
    float s[8];
#pragma unroll
    for (int j = 0; j < 8; j++) s[j] = 0.f;
    for (; e + 1 < e1; e += 2) {
        int s0 = __ldg(&csrc[e]);
        int s1 = __ldg(&csrc[e + 1]);
        float d0 = __ldg(&dinv[s0]);
        float d1 = __ldg(&dinv[s1]);
        uint4 v0 = __ldg(&XH[s0 * 8 + g]);
        uint4 v1 = __ldg(&XH[s1 * 8 + g]);
        float f0[8], f1[8];
        h8tof(v0, f0);
        h8tof(v1, f1);
#pragma unroll
        for (int j = 0; j < 8; j++)
            s[j] = fmaf(f0[j], d0, fmaf(f1[j], d1, s[j]));
    }
    if (e < e1) {
        int s0 = __ldg(&csrc[e]);
        float d0 = __ldg(&dinv[s0]);
        uint4 v0 = __ldg(&XH[s0 * 8 + g]);
        float f0[8];
        h8tof(v0, f0);
#pragma unroll
        for (int j = 0; j < 8; j++) s[j] = fmaf(f0[j], d0, s[j]);
    }
    float di = __ldg(&dinv[node]);
    float di2 = di * di;
    uint4 sv = __ldg(&XH[node * 8 + g]);
    float fs[8];
    h8tof(sv, fs);
    float z[8];
#pragma unroll
    for (int j = 0; j < 8; j++) z[j] = fmaf(s[j], di, fs[j] * di2);
    Z[node * 16 + g * 2]     = make_float4(z[0], z[1], z[2], z[3]);
    Z[node * 16 + g * 2 + 1] = make_float4(z[4], z[5], z[6], z[7]);
}

// ---------------------------------------------------------------------------
// layer-2 aggregate-after on fp16 messages (dim 40 = 5 groups of 8 halves):
//   A2[node] = AGG[node] + (sum of Hs[src]) * dinv[node]    -> stored fp16
// AGG (fp32) pre-holds self-loop + bias from gemm2's epilogue.
// ---------------------------------------------------------------------------
__global__ void agg2_h(const uint4* __restrict__ Hs,
                       const int* __restrict__ cur,
                       const int* __restrict__ csrc,
                       const float* __restrict__ dinv,
                       const float4* __restrict__ AGG,
                       uint4* __restrict__ A2, int n) {
    int idx = blockIdx.x * blockDim.x + threadIdx.x;
    int node = idx / 5;
    int g = idx - node * 5;
    cudaGridDependencySynchronize();
    if (node >= n) return;
    int e = node << CAP_LOG;
    int e1 = __ldg(&cur[node]);
    float s[8];
#pragma unroll
    for (int j = 0; j < 8; j++) s[j] = 0.f;
    for (; e + 1 < e1; e += 2) {
        int s0 = __ldg(&csrc[e]);
        int s1 = __ldg(&csrc[e + 1]);
        uint4 v0 = __ldg(&Hs[s0 * 5 + g]);
        uint4 v1 = __ldg(&Hs[s1 * 5 + g]);
        float f0[8], f1[8];
        h8tof(v0, f0);
        h8tof(v1, f1);
#pragma unroll
        for (int j = 0; j < 8; j++) s[j] += f0[j] + f1[j];
    }
    if (e < e1) {
        int s0 = __ldg(&csrc[e]);
        uint4 v0 = __ldg(&Hs[s0 * 5 + g]);
        float f0[8];
        h8tof(v0, f0);
#pragma unroll
        for (int j = 0; j < 8; j++) s[j] += f0[j];
    }
    float nd = __ldg(&dinv[node]);
    float4 a0 = __ldg(&AGG[node * 10 + 2 * g]);
    float4 a1 = __ldg(&AGG[node * 10 + 2 * g + 1]);
    float r[8];
    r[0] = fmaf(s[0], nd, a0.x); r[1] = fmaf(s[1], nd, a0.y);
    r[2] = fmaf(s[2], nd, a0.z); r[3] = fmaf(s[3], nd, a0.w);
    r[4] = fmaf(s[4], nd, a1.x); r[5] = fmaf(s[5], nd, a1.y);
    r[6] = fmaf(s[6], nd, a1.z); r[7] = fmaf(s[7], nd, a1.w);
    A2[node * 5 + g] = ftoh8(r);
}

// ---------------------------------------------------------------------------
// layer-3 aggregate-first on fp16 A2 (leaky applied post-dequant):
//   Z3[i] = dinv[i]*(sum_s dinv[s]*leaky(A2[s])) + dinv[i]^2*leaky(A2[i])
// ---------------------------------------------------------------------------
__device__ __forceinline__ float lk(float v) {
    return (v > 0.f) ? v : 0.01f * v;
}

__global__ void agg3_h(const uint4* __restrict__ A2,
                       const int* __restrict__ cur,
                       const int* __restrict__ csrc,
                       const float* __restrict__ dinv,
                       float4* __restrict__ Z, int n) {
    int idx = blockIdx.x * blockDim.x + threadIdx.x;
    int node = idx / 5;
    int g = idx - node * 5;
    cudaGridDependencySynchronize();
    if (node >= n) return;
    int e = node << CAP_LOG;
    int e1 = __ldg(&cur[node]);
    float s[8];
#pragma unroll
    for (int j = 0; j < 8; j++) s[j] = 0.f;
    for (; e + 1 < e1; e += 2) {
        int s0 = __ldg(&csrc[e]);
        int s1 = __ldg(&csrc[e + 1]);
        float d0 = __ldg(&dinv[s0]);
        float d1 = __ldg(&dinv[s1]);
        uint4 v0 = __ldg(&A2[s0 * 5 + g]);
        uint4 v1 = __ldg(&A2[s1 * 5 + g]);
        float f0[8], f1[8];
        h8tof(v0, f0);
        h8tof(v1, f1);
#pragma unroll
        for (int j = 0; j < 8; j++)
            s[j] = fmaf(lk(f0[j]), d0, fmaf(lk(f1[j]), d1, s[j]));
    }
    if (e < e1) {
        int s0 = __ldg(&csrc[e]);
        float d0 = __ldg(&dinv[s0]);
        uint4 v0 = __ldg(&A2[s0 * 5 + g]);
        float f0[8];
        h8tof(v0, f0);
#pragma unroll
        for (int j = 0; j < 8; j++) s[j] = fmaf(lk(f0[j]), d0, s[j]);
    }
    float di = __ldg(&dinv[node]);
    float di2 = di * di;
    uint4 sv = __ldg(&A2[node * 5 + g]);
    float fs[8];
    h8tof(sv, fs);
    float z[8];
#pragma unroll
    for (int j = 0; j < 8; j++) z[j] = fmaf(s[j], di, lk(fs[j]) * di2);
    Z[node * 10 + 2 * g]     = make_float4(z[0], z[1], z[2], z[3]);
    Z[node * 10 + 2 * g + 1] = make_float4(z[4], z[5], z[6], z[7]);
}

// ---------------------------------------------------------------------------
// Register-tiled fused GEMM.
//   acc = leaky?(X[rows]) @ W       TM x TN tile per thread, f32x2 FMAs
// GCNEPI: Hs = acc*dinv (fp16 if HALFHS), AGG = acc*dinv^2 + b (fp32)
// else:   OUT = acc + b (fp32)
// ---------------------------------------------------------------------------
template <int K, int DOUT, int BM, int BK, int TM, int TN, int THREADS,
          bool LEAKY, bool GCNEPI, bool HALFHS>
__global__ __launch_bounds__(THREADS)
void gemm_fused(const float* __restrict__ X,
                const float* __restrict__ W,
                const float* __restrict__ b,
                const float* __restrict__ dinv,
                void* __restrict__ Hs,
                float* __restrict__ AGG, int n) {
    constexpr int COLG = DOUT / TN;
    constexpr int ROWG = THREADS / COLG;
    constexpr int NP = TN / 2;
    static_assert(COLG * TN == DOUT, "tn");
    static_assert(COLG * ROWG == THREADS, "thr");
    static_assert(ROWG * TM == BM, "bm");
    static_assert(K % BK == 0, "bk");

    __shared__ __align__(16) float Ws[K * DOUT];
    __shared__ __align__(16) float Xs[BM * (BK + 1)];

    const int tid = threadIdx.x;
    const int row0 = blockIdx.x * BM;
    const int nrows = min(BM, n - row0);

    for (int i = tid; i < K * DOUT; i += THREADS) Ws[i] = W[i];

    const int colg = tid % COLG;
    const int rowg = tid / COLG;
    const int col0 = colg * TN;
    const int r0 = rowg * TM;

    unsigned long long acc[TM][NP];
#pragma unroll
    for (int i = 0; i < TM; i++)
#pragma unroll
        for (int jp = 0; jp < NP; jp++) acc[i][jp] = 0ULL;

    cudaGridDependencySynchronize();

    for (int k0 = 0; k0 < K; k0 += BK) {
        __syncthreads();
        for (int i = tid; i < nrows * BK; i += THREADS) {
            int r = i / BK, c = i - r * BK;
            float v = __ldg(&X[(size_t)(row0 + r) * K + k0 + c]);
            if (LEAKY) v = (v > 0.0f) ? v : 0.01f * v;
            Xs[r * (BK + 1) + c] = v;
        }
        __syncthreads();

#pragma unroll 4
        for (int k = 0; k < BK; k++) {
            unsigned long long wv[NP];
            const unsigned long long* wr =
                (const unsigned long long*)&Ws[(k0 + k) * DOUT + col0];
#pragma unroll
            for (int jp = 0; jp < NP; jp++) wv[jp] = wr[jp];
#pragma unroll
            for (int i = 0; i < TM; i++) {
                float xv = Xs[(r0 + i) * (BK + 1) + k];
                unsigned long long xp;
                asm("mov.b64 %0, {%1, %1};" : "=l"(xp) : "f"(xv));
#pragma unroll
                for (int jp = 0; jp < NP; jp++) {
                    asm("fma.rn.f32x2 %0, %1, %2, %0;"
                        : "+l"(acc[i][jp]) : "l"(xp), "l"(wv[jp]));
                }
            }
        }
    }

#pragma unroll
    for (int i = 0; i < TM; i++) {
        int row = row0 + r0 + i;
        if (row >= n) break;
        if (GCNEPI) {
            float di = dinv[row];
            float di2 = di * di;
            float* agr = AGG + (size_t)row * DOUT + col0;
#pragma unroll
            for (int jp = 0; jp < NP; jp++) {
                float lo, hi;
                asm("mov.b64 {%0, %1}, %2;" : "=f"(lo), "=f"(hi) : "l"(acc[i][jp]));
                float blo = __ldg(&b[col0 + 2 * jp]);
                float bhi = __ldg(&b[col0 + 2 * jp + 1]);
                if (HALFHS) {
                    unsigned* hsr = (unsigned*)Hs +
                                    (size_t)row * (DOUT / 2) + col0 / 2;
                    __half2 hh = __floats2half2_rn(lo * di, hi * di);
                    hsr[jp] = *reinterpret_cast<unsigned*>(&hh);
                } else {
                    float2* hsr = (float2*)((float*)Hs +
                                            (size_t)row * DOUT + col0);
                    hsr[jp] = make_float2(lo * di, hi * di);
                }
                ((float2*)agr)[jp] = make_float2(lo * di2 + blo,
                                                 hi * di2 + bhi);
            }
        } else {
            float2* outr = (float2*)(AGG + (size_t)row * DOUT + col0);
#pragma unroll
            for (int jp = 0; jp < NP; jp++) {
                float lo, hi;
                asm("mov.b64 {%0, %1}, %2;" : "=f"(lo), "=f"(hi) : "l"(acc[i][jp]));
                float blo = __ldg(&b[col0 + 2 * jp]);
                float bhi = __ldg(&b[col0 + 2 * jp + 1]);
                outr[jp] = make_float2(lo + blo, hi + bhi);
            }
        }
    }
}

// ---------------------------------------------------------------------------
// gemm3 + classifier head, fused (fp32 in/out, unchanged).
// ---------------------------------------------------------------------------
__global__ __launch_bounds__(160)
void gemm3_head(const float* __restrict__ X,
                const float* __restrict__ W,
                const float* __restrict__ b,
                const float* __restrict__ Wl,
                const float* __restrict__ bl,
                float* __restrict__ out, int n) {
    constexpr int K = 40, DOUT = 50, BM = 128, BK = 20;
    constexpr int TM = 4, TN = 10, THREADS = 160, COLG = 5, NP = TN / 2;
    constexpr int VP = DOUT + 3;

    __shared__ __align__(16) float Ws[K * DOUT];
    __shared__ __align__(16) float Xs[BM * (BK + 1)];
    __shared__ float Wl_s[500];
    __shared__ float bl_s[10];
    __shared__ float bs[DOUT];
    __shared__ float vrow[BM * VP];

    const int tid = threadIdx.x;
    const int row0 = blockIdx.x * BM;
    const int nrows = min(BM, n - row0);

    for (int i = tid; i < K * DOUT; i += THREADS) Ws[i] = W[i];
    for (int i = tid; i < 500; i += THREADS) Wl_s[i] = Wl[i];
    if (tid < 10) bl_s[tid] = bl[tid];
    if (tid < DOUT) bs[tid] = b[tid];

    const int colg = tid % COLG;
    const int rowg = tid / COLG;
    const int col0 = colg * TN;
    const int r0 = rowg * TM;

    unsigned long long acc[TM][NP];
#pragma unroll
    for (int i = 0; i < TM; i++)
#pragma unroll
        for (int jp = 0; jp < NP; jp++) acc[i][jp] = 0ULL;

    cudaGridDependencySynchronize();

    for (int k0 = 0; k0 < K; k0 += BK) {
        __syncthreads();
        for (int i = tid; i < nrows * BK; i += THREADS) {
            int r = i / BK, c = i - r * BK;
            Xs[r * (BK + 1) + c] = __ldg(&X[(size_t)(row0 + r) * K + k0 + c]);
        }
        __syncthreads();

#pragma unroll 4
        for (int k = 0; k < BK; k++) {
            unsigned long long wv[NP];
            const unsigned long long* wr =
                (const unsigned long long*)&Ws[(k0 + k) * DOUT + col0];
#pragma unroll
            for (int jp = 0; jp < NP; jp++) wv[jp] = wr[jp];
#pragma unroll
            for (int i = 0; i < TM; i++) {
                float xv = Xs[(r0 + i) * (BK + 1) + k];
                unsigned long long xp;
                asm("mov.b64 %0, {%1, %1};" : "=l"(xp) : "f"(xv));
#pragma unroll
                for (int jp = 0; jp < NP; jp++) {
                    asm("fma.rn.f32x2 %0, %1, %2, %0;"
                        : "+l"(acc[i][jp]) : "l"(xp), "l"(wv[jp]));
                }
            }
        }
    }

#pragma unroll
    for (int i = 0; i < TM; i++) {
        int r = r0 + i;
#pragma unroll
        for (int jp = 0; jp < NP; jp++) {
            float lo, hi;
            asm("mov.b64 {%0, %1}, %2;" : "=f"(lo), "=f"(hi) : "l"(acc[i][jp]));
            lo += bs[col0 + 2 * jp];
            hi += bs[col0 + 2 * jp + 1];
            lo = (lo > 0.f) ? lo : 0.01f * lo;
            hi = (hi > 0.f) ? hi : 0.01f * hi;
            vrow[r * VP + col0 + 2 * jp] = lo;
            vrow[r * VP + col0 + 2 * jp + 1] = hi;
        }
    }
    __syncthreads();

    if (tid < nrows) {
        const float* vr = &vrow[tid * VP];
        float logits[10];
#pragma unroll
        for (int j = 0; j < 10; j++) logits[j] = bl_s[j];
#pragma unroll
        for (int k = 0; k < DOUT; k++) {
            float v = vr[k];
#pragma unroll
            for (int j = 0; j < 10; j++)
                logits[j] = fmaf(v, Wl_s[k * 10 + j], logits[j]);
        }
        float mx = logits[0];
#pragma unroll
        for (int j = 1; j < 10; j++) mx = fmaxf(mx, logits[j]);
        float s = 0.f;
#pragma unroll
        for (int j = 0; j < 10; j++) s += __expf(logits[j] - mx);
        float lse = mx + __logf(s);
        float* outr = out + (size_t)(row0 + tid) * 10;
#pragma unroll
        for (int j = 0; j < 10; j++) outr[j] = logits[j] - lse;
    }
}

// ---------------------------------------------------------------------------
// launch
// ---------------------------------------------------------------------------
extern "C" void kernel_launch(void* const* d_in, const int* in_sizes, int n_in,
                              void* d_out, int out_size) {
    const float* x = (const float*)d_in[0];
    const int* edge = (const int*)d_in[1];  // int32 (JAX downcast)
    const float* W1 = (const float*)d_in[2];
    const float* b1 = (const float*)d_in[3];
    const float* W2 = (const float*)d_in[4];
    const float* b2 = (const float*)d_in[5];
    const float* W3 = (const float*)d_in[6];
    const float* b3 = (const float*)d_in[7];
    const float* Wl = (const float*)d_in[8];
    const float* bl = (const float*)d_in[9];
    float* out = (float*)d_out;

    const int n = in_sizes[0] / 64;  // 100000
    const int E = in_sizes[1] / 2;   // 1000000
    const int* src = edge;
    const int* dst = edge + E;

    float *bufA, *bufB, *bufC, *dinv;
    int *cur, *csrc;
    __half *hX, *hM, *hA2;
    cudaGetSymbolAddress((void**)&bufA, g_bufA);
    cudaGetSymbolAddress((void**)&bufB, g_bufB);
    cudaGetSymbolAddress((void**)&bufC, g_bufC);
    cudaGetSymbolAddress((void**)&dinv, g_dinv);
    cudaGetSymbolAddress((void**)&cur, g_cur);
    cudaGetSymbolAddress((void**)&csrc, g_csrc);
    cudaGetSymbolAddress((void**)&hX, g_hX);
    cudaGetSymbolAddress((void**)&hM, g_hM);
    cudaGetSymbolAddress((void**)&hA2, g_hA2);

    const int T = 256;

    // ---- kernel 1: cursor init + x->fp16 (fused; no dependency sync) ----
    pdl_launch(init_convert, cdiv(n * 8, T), T,
               (const float4*)x, (uint4*)hX, cur, n);

    // ---- bucket CSR scatter + dinv ----
    pdl_launch(csr_scatter, cdiv(E, T), T,
               (const int*)src, (const int*)dst, cur, csrc, E);
    pdl_launch(dinv_fin, cdiv(n, T), T, (const int*)cur, dinv, n);

    // ---- layer 1: fp16 aggregate-first, then GEMM 64->80 (fp32) ----
    pdl_launch(agg_pre1_h, cdiv(n * 8, T), T,
               (const uint4*)hX, (const int*)cur, (const int*)csrc,
               (const float*)dinv, (float4*)bufB, n);
    pdl_launch(gemm_fused<64, 80, 128, 32, 4, 10, 256, false, false, false>,
               cdiv(n, 128), 256,
               (const float*)bufB, W1, b1, (const float*)dinv,
               (void*)bufA, bufC, n);

    // ---- layer 2: GEMM 80->40 (fp16 messages), aggregate-after -> A2 fp16 --
    pdl_launch(gemm_fused<80, 40, 256, 20, 4, 10, 256, true, true, true>,
               cdiv(n, 256), 256,
               (const float*)bufC, W2, b2, (const float*)dinv,
               (void*)hM, bufA, n);
    pdl_launch(agg2_h, cdiv(n * 5, T), T,
               (const uint4*)hM, (const int*)cur, (const int*)csrc,
               (const float*)dinv, (const float4*)bufA, (uint4*)hA2, n);

    // ---- layer 3: fp16 aggregate-first (leaky fused) -> Z3 fp32 ----
    pdl_launch(agg3_h, cdiv(n * 5, T), T,
               (const uint4*)hA2, (const int*)cur, (const int*)csrc,
               (const float*)dinv, (float4*)bufB, n);

    // ---- gemm3 (40->50) fused with classifier head + log_softmax ----
    pdl_launch(gemm3_head, cdiv(n, 128), 160,
               (const float*)bufB, W3, b3, Wl, bl, out, n);
}

// round 17
// speedup vs baseline: 1.0324x; 1.0324x over previous
#include <cuda_runtime.h>
#include <cuda_fp16.h>
#include <math.h>

// ---------------------------------------------------------------------------
// GCNClassifier: 3x GCNConv (+leaky relu) + linear + log_softmax
// N = 100000, E = 1000000, dims 64 -> 80 -> 40 -> 50 -> 10
// Strategy: bucket CSR (CAP=64/node), fp16 storage for gathered message
// buffers (x, Hs2, A2) with fp32 accumulation, 4-halves-per-thread gathers
// (max thread parallelism at half the bytes), register-tiled fused GEMMs
// with f32x2 FMAs. Layers 1 and 3 aggregate BEFORE their GEMM; classifier
// head fused into gemm3. All kernels chained with PDL.
// ---------------------------------------------------------------------------

#define N_NODES 100000
#define CAP     64
#define CAP_LOG 6
#define MAX_DIM 80

__device__ float  g_bufA[N_NODES * MAX_DIM];
__device__ float  g_bufB[N_NODES * MAX_DIM];
__device__ float  g_bufC[N_NODES * MAX_DIM];
__device__ float  g_dinv[N_NODES];
__device__ int    g_cur[N_NODES];
__device__ int    g_csrc[N_NODES * CAP];
__device__ __align__(16) __half g_hX[N_NODES * 64];
__device__ __align__(16) __half g_hM[N_NODES * 40];
__device__ __align__(16) __half g_hA2[N_NODES * 40];

static inline int cdiv(int a, int b) { return (a + b - 1) / b; }

// ---------------------------------------------------------------------------
// PDL launch helper
// ---------------------------------------------------------------------------
template <typename... Args>
static void pdl_launch(void (*kern)(Args...), int grid, int block,
                       Args... args) {
    cudaLaunchConfig_t cfg = {};
    cfg.gridDim = dim3((unsigned)grid);
    cfg.blockDim = dim3((unsigned)block);
    cudaLaunchAttribute attr[1];
    attr[0].id = cudaLaunchAttributeProgrammaticStreamSerialization;
    attr[0].val.programmaticStreamSerializationAllowed = 1;
    cfg.attrs = attr;
    cfg.numAttrs = 1;
    cudaLaunchKernelEx(&cfg, kern, args...);
}

// ---------------------------------------------------------------------------
// half4 <-> float4 helpers (uint2 = 4 halves)
// ---------------------------------------------------------------------------
__device__ __forceinline__ void h4tof(uint2 v, float f[4]) {
    __half2 h;
    *reinterpret_cast<unsigned*>(&h) = v.x;
    float2 t = __half22float2(h); f[0] = t.x; f[1] = t.y;
    *reinterpret_cast<unsigned*>(&h) = v.y;
    t = __half22float2(h); f[2] = t.x; f[3] = t.y;
}

__device__ __forceinline__ uint2 ftoh4(const float f[4]) {
    uint2 o;
    __half2 h;
    h = __floats2half2_rn(f[0], f[1]); o.x = *reinterpret_cast<unsigned*>(&h);
    h = __floats2half2_rn(f[2], f[3]); o.y = *reinterpret_cast<unsigned*>(&h);
    return o;
}

// ---------------------------------------------------------------------------
// kernel 1: bucket cursor init + x -> fp16 conversion (fused). No PDL sync.
// ---------------------------------------------------------------------------
__global__ void init_convert(const float4* __restrict__ X4,
                             uint2* __restrict__ XH, int* cur, int n) {
    int i = blockIdx.x * blockDim.x + threadIdx.x;
    if (i < n) cur[i] = i << CAP_LOG;
    if (i >= n * 16) return;
    float4 a = __ldg(&X4[i]);
    float f[4] = {a.x, a.y, a.z, a.w};
    XH[i] = ftoh4(f);
}

__global__ void csr_scatter(const int* __restrict__ src,
                            const int* __restrict__ dst,
                            int* cur, int* csrc, int E) {
    int e = blockIdx.x * blockDim.x + threadIdx.x;
    int s = 0, d = 0;
    if (e < E) {
        s = __ldg(&src[e]);
        d = __ldg(&dst[e]);
    }
    cudaGridDependencySynchronize();
    if (e < E) {
        int pos = atomicAdd(&cur[d], 1);
        csrc[pos] = s;
    }
}

__global__ void dinv_fin(const int* __restrict__ cur, float* dinv, int n) {
    int i = blockIdx.x * blockDim.x + threadIdx.x;
    cudaGridDependencySynchronize();
    if (i < n) {
        int deg = cur[i] - (i << CAP_LOG);
        dinv[i] = rsqrtf((float)deg + 1.0f);
    }
}

// ---------------------------------------------------------------------------
// layer-1 aggregate-first on fp16 x (dim 64 = 16 groups of 4 halves):
//   Z1[i] = dinv[i]*(sum_s dinv[s]*xh[s]) + dinv[i]^2 * xh[i]   (fp32 accum)
// ---------------------------------------------------------------------------
__global__ void agg_pre1_h(const uint2* __restrict__ XH,
                           const int* __restrict__ cur,
                           const int* __restrict__ csrc,
                           const float* __restrict__ dinv,
                           float4* __restrict__ Z, int n) {
    int idx = blockIdx.x * blockDim.x + threadIdx.x;
    int node = idx >> 4;
    int g = idx & 15;
    cudaGridDependencySynchronize();
    if (node >= n) return;
    int e = node << CAP_LOG;
    int e1 = __ldg(&cur[node]);
    float s[4] = {0.f, 0.f, 0.f, 0.f};
    for (; e + 1 < e1; e += 2) {
        int s0 = __ldg(&csrc[e]);
        int s1 = __ldg(&csrc[e + 1]);
        float d0 = __ldg(&dinv[s0]);
        float d1 = __ldg(&dinv[s1]);
        uint2 v0 = __ldg(&XH[s0 * 16 + g]);
        uint2 v1 = __ldg(&XH[s1 * 16 + g]);
        float f0[4], f1[4];
        h4tof(v0, f0);
        h4tof(v1, f1);
#pragma unroll
        for (int j = 0; j < 4; j++)
            s[j] = fmaf(f0[j], d0, fmaf(f1[j], d1, s[j]));
    }
    if (e < e1) {
        int s0 = __ldg(&csrc[e]);
        float d0 = __ldg(&dinv[s0]);
        uint2 v0 = __ldg(&XH[s0 * 16 + g]);
        float f0[4];
        h4tof(v0, f0);
#pragma unroll
        for (int j = 0; j < 4; j++) s[j] = fmaf(f0[j], d0, s[j]);
    }
    float di = __ldg(&dinv[node]);
    float di2 = di * di;
    uint2 sv = __ldg(&XH[node * 16 + g]);
    float fs[4];
    h4tof(sv, fs);
    Z[node * 16 + g] = make_float4(fmaf(s[0], di, fs[0] * di2),
                                   fmaf(s[1], di, fs[1] * di2),
                                   fmaf(s[2], di, fs[2] * di2),
                                   fmaf(s[3], di, fs[3] * di2));
}

// ---------------------------------------------------------------------------
// layer-2 aggregate-after on fp16 messages (dim 40 = 10 groups of 4 halves):
//   A2[node] = AGG[node] + (sum of Hs[src]) * dinv[node]    -> stored fp16
// ---------------------------------------------------------------------------
__global__ void agg2_h(const uint2* __restrict__ Hs,
                       const int* __restrict__ cur,
                       const int* __restrict__ csrc,
                       const float* __restrict__ dinv,
                       const float4* __restrict__ AGG,
                       uint2* __restrict__ A2, int n) {
    int idx = blockIdx.x * blockDim.x + threadIdx.x;
    int node = idx / 10;
    int g = idx - node * 10;
    cudaGridDependencySynchronize();
    if (node >= n) return;
    int e = node << CAP_LOG;
    int e1 = __ldg(&cur[node]);
    float s[4] = {0.f, 0.f, 0.f, 0.f};
    for (; e + 1 < e1; e += 2) {
        int s0 = __ldg(&csrc[e]);
        int s1 = __ldg(&csrc[e + 1]);
        uint2 v0 = __ldg(&Hs[s0 * 10 + g]);
        uint2 v1 = __ldg(&Hs[s1 * 10 + g]);
        float f0[4], f1[4];
        h4tof(v0, f0);
        h4tof(v1, f1);
#pragma unroll
        for (int j = 0; j < 4; j++) s[j] += f0[j] + f1[j];
    }
    if (e < e1) {
        int s0 = __ldg(&csrc[e]);
        uint2 v0 = __ldg(&Hs[s0 * 10 + g]);
        float f0[4];
        h4tof(v0, f0);
#pragma unroll
        for (int j = 0; j < 4; j++) s[j] += f0[j];
    }
    float nd = __ldg(&dinv[node]);
    float4 a0 = __ldg(&AGG[node * 10 + g]);
    float r[4];
    r[0] = fmaf(s[0], nd, a0.x);
    r[1] = fmaf(s[1], nd, a0.y);
    r[2] = fmaf(s[2], nd, a0.z);
    r[3] = fmaf(s[3], nd, a0.w);
    A2[node * 10 + g] = ftoh4(r);
}

// ---------------------------------------------------------------------------
// layer-3 aggregate-first on fp16 A2 (leaky applied post-dequant):
//   Z3[i] = dinv[i]*(sum_s dinv[s]*leaky(A2[s])) + dinv[i]^2*leaky(A2[i])
// ---------------------------------------------------------------------------
__device__ __forceinline__ float lk(float v) {
    return (v > 0.f) ? v : 0.01f * v;
}

__global__ void agg3_h(const uint2* __restrict__ A2,
                       const int* __restrict__ cur,
                       const int* __restrict__ csrc,
                       const float* __restrict__ dinv,
                       float4* __restrict__ Z, int n) {
    int idx = blockIdx.x * blockDim.x + threadIdx.x;
    int node = idx / 10;
    int g = idx - node * 10;
    cudaGridDependencySynchronize();
    if (node >= n) return;
    int e = node << CAP_LOG;
    int e1 = __ldg(&cur[node]);
    float s[4] = {0.f, 0.f, 0.f, 0.f};
    for (; e + 1 < e1; e += 2) {
        int s0 = __ldg(&csrc[e]);
        int s1 = __ldg(&csrc[e + 1]);
        float d0 = __ldg(&dinv[s0]);
        float d1 = __ldg(&dinv[s1]);
        uint2 v0 = __ldg(&A2[s0 * 10 + g]);
        uint2 v1 = __ldg(&A2[s1 * 10 + g]);
        float f0[4], f1[4];
        h4tof(v0, f0);
        h4tof(v1, f1);
#pragma unroll
        for (int j = 0; j < 4; j++)
            s[j] = fmaf(lk(f0[j]), d0, fmaf(lk(f1[j]), d1, s[j]));
    }
    if (e < e1) {
        int s0 = __ldg(&csrc[e]);
        float d0 = __ldg(&dinv[s0]);
        uint2 v0 = __ldg(&A2[s0 * 10 + g]);
        float f0[4];
        h4tof(v0, f0);
#pragma unroll
        for (int j = 0; j < 4; j++) s[j] = fmaf(lk(f0[j]), d0, s[j]);
    }
    float di = __ldg(&dinv[node]);
    float di2 = di * di;
    uint2 sv = __ldg(&A2[node * 10 + g]);
    float fs[4];
    h4tof(sv, fs);
    Z[node * 10 + g] = make_float4(fmaf(s[0], di, lk(fs[0]) * di2),
                                   fmaf(s[1], di, lk(fs[1]) * di2),
                                   fmaf(s[2], di, lk(fs[2]) * di2),
                                   fmaf(s[3], di, lk(fs[3]) * di2));
}

// ---------------------------------------------------------------------------
// Register-tiled fused GEMM.
//   acc = leaky?(X[rows]) @ W       TM x TN tile per thread, f32x2 FMAs
// GCNEPI: Hs = acc*dinv (fp16 if HALFHS), AGG = acc*dinv^2 + b (fp32)
// else:   OUT = acc + b (fp32)
// ---------------------------------------------------------------------------
template <int K, int DOUT, int BM, int BK, int TM, int TN, int THREADS,
          bool LEAKY, bool GCNEPI, bool HALFHS>
__global__ __launch_bounds__(THREADS)
void gemm_fused(const float* __restrict__ X,
                const float* __restrict__ W,
                const float* __restrict__ b,
                const float* __restrict__ dinv,
                void* __restrict__ Hs,
                float* __restrict__ AGG, int n) {
    constexpr int COLG = DOUT / TN;
    constexpr int ROWG = THREADS / COLG;
    constexpr int NP = TN / 2;
    static_assert(COLG * TN == DOUT, "tn");
    static_assert(COLG * ROWG == THREADS, "thr");
    static_assert(ROWG * TM == BM, "bm");
    static_assert(K % BK == 0, "bk");

    __shared__ __align__(16) float Ws[K * DOUT];
    __shared__ __align__(16) float Xs[BM * (BK + 1)];

    const int tid = threadIdx.x;
    const int row0 = blockIdx.x * BM;
    const int nrows = min(BM, n - row0);

    for (int i = tid; i < K * DOUT; i += THREADS) Ws[i] = W[i];

    const int colg = tid % COLG;
    const int rowg = tid / COLG;
    const int col0 = colg * TN;
    const int r0 = rowg * TM;

    unsigned long long acc[TM][NP];
#pragma unroll
    for (int i = 0; i < TM; i++)
#pragma unroll
        for (int jp = 0; jp < NP; jp++) acc[i][jp] = 0ULL;

    cudaGridDependencySynchronize();

    for (int k0 = 0; k0 < K; k0 += BK) {
        __syncthreads();
        for (int i = tid; i < nrows * BK; i += THREADS) {
            int r = i / BK, c = i - r * BK;
            float v = __ldg(&X[(size_t)(row0 + r) * K + k0 + c]);
            if (LEAKY) v = (v > 0.0f) ? v : 0.01f * v;
            Xs[r * (BK + 1) + c] = v;
        }
        __syncthreads();

#pragma unroll 4
        for (int k = 0; k < BK; k++) {
            unsigned long long wv[NP];
            const unsigned long long* wr =
                (const unsigned long long*)&Ws[(k0 + k) * DOUT + col0];
#pragma unroll
            for (int jp = 0; jp < NP; jp++) wv[jp] = wr[jp];
#pragma unroll
            for (int i = 0; i < TM; i++) {
                float xv = Xs[(r0 + i) * (BK + 1) + k];
                unsigned long long xp;
                asm("mov.b64 %0, {%1, %1};" : "=l"(xp) : "f"(xv));
#pragma unroll
                for (int jp = 0; jp < NP; jp++) {
                    asm("fma.rn.f32x2 %0, %1, %2, %0;"
                        : "+l"(acc[i][jp]) : "l"(xp), "l"(wv[jp]));
                }
            }
        }
    }

#pragma unroll
    for (int i = 0; i < TM; i++) {
        int row = row0 + r0 + i;
        if (row >= n) break;
        if (GCNEPI) {
            float di = dinv[row];
            float di2 = di * di;
            float* agr = AGG + (size_t)row * DOUT + col0;
#pragma unroll
            for (int jp = 0; jp < NP; jp++) {
                float lo, hi;
                asm("mov.b64 {%0, %1}, %2;" : "=f"(lo), "=f"(hi) : "l"(acc[i][jp]));
                float blo = __ldg(&b[col0 + 2 * jp]);
                float bhi = __ldg(&b[col0 + 2 * jp + 1]);
                if (HALFHS) {
                    unsigned* hsr = (unsigned*)Hs +
                                    (size_t)row * (DOUT / 2) + col0 / 2;
                    __half2 hh = __floats2half2_rn(lo * di, hi * di);
                    hsr[jp] = *reinterpret_cast<unsigned*>(&hh);
                } else {
                    float2* hsr = (float2*)((float*)Hs +
                                            (size_t)row * DOUT + col0);
                    hsr[jp] = make_float2(lo * di, hi * di);
                }
                ((float2*)agr)[jp] = make_float2(lo * di2 + blo,
                                                 hi * di2 + bhi);
            }
        } else {
            float2* outr = (float2*)(AGG + (size_t)row * DOUT + col0);
#pragma unroll
            for (int jp = 0; jp < NP; jp++) {
                float lo, hi;
                asm("mov.b64 {%0, %1}, %2;" : "=f"(lo), "=f"(hi) : "l"(acc[i][jp]));
                float blo = __ldg(&b[col0 + 2 * jp]);
                float bhi = __ldg(&b[col0 + 2 * jp + 1]);
                outr[jp] = make_float2(lo + blo, hi + bhi);
            }
        }
    }
}

// ---------------------------------------------------------------------------
// gemm3 + classifier head, fused (fp32 in/out).
// ---------------------------------------------------------------------------
__global__ __launch_bounds__(160)
void gemm3_head(const float* __restrict__ X,
                const float* __restrict__ W,
                const float* __restrict__ b,
                const float* __restrict__ Wl,
                const float* __restrict__ bl,
                float* __restrict__ out, int n) {
    constexpr int K = 40, DOUT = 50, BM = 128, BK = 20;
    constexpr int TM = 4, TN = 10, THREADS = 160, COLG = 5, NP = TN / 2;
    constexpr int VP = DOUT + 3;

    __shared__ __align__(16) float Ws[K * DOUT];
    __shared__ __align__(16) float Xs[BM * (BK + 1)];
    __shared__ float Wl_s[500];
    __shared__ float bl_s[10];
    __shared__ float bs[DOUT];
    __shared__ float vrow[BM * VP];

    const int tid = threadIdx.x;
    const int row0 = blockIdx.x * BM;
    const int nrows = min(BM, n - row0);

    for (int i = tid; i < K * DOUT; i += THREADS) Ws[i] = W[i];
    for (int i = tid; i < 500; i += THREADS) Wl_s[i] = Wl[i];
    if (tid < 10) bl_s[tid] = bl[tid];
    if (tid < DOUT) bs[tid] = b[tid];

    const int colg = tid % COLG;
    const int rowg = tid / COLG;
    const int col0 = colg * TN;
    const int r0 = rowg * TM;

    unsigned long long acc[TM][NP];
#pragma unroll
    for (int i = 0; i < TM; i++)
#pragma unroll
        for (int jp = 0; jp < NP; jp++) acc[i][jp] = 0ULL;

    cudaGridDependencySynchronize();

    for (int k0 = 0; k0 < K; k0 += BK) {
        __syncthreads();
        for (int i = tid; i < nrows * BK; i += THREADS) {
            int r = i / BK, c = i - r * BK;
            Xs[r * (BK + 1) + c] = __ldg(&X[(size_t)(row0 + r) * K + k0 + c]);
        }
        __syncthreads();

#pragma unroll 4
        for (int k = 0; k < BK; k++) {
            unsigned long long wv[NP];
            const unsigned long long* wr =
                (const unsigned long long*)&Ws[(k0 + k) * DOUT + col0];
#pragma unroll
            for (int jp = 0; jp < NP; jp++) wv[jp] = wr[jp];
#pragma unroll
            for (int i = 0; i < TM; i++) {
                float xv = Xs[(r0 + i) * (BK + 1) + k];
                unsigned long long xp;
                asm("mov.b64 %0, {%1, %1};" : "=l"(xp) : "f"(xv));
#pragma unroll
                for (int jp = 0; jp < NP; jp++) {
                    asm("fma.rn.f32x2 %0, %1, %2, %0;"
                        : "+l"(acc[i][jp]) : "l"(xp), "l"(wv[jp]));
                }
            }
        }
    }

#pragma unroll
    for (int i = 0; i < TM; i++) {
        int r = r0 + i;
#pragma unroll
        for (int jp = 0; jp < NP; jp++) {
            float lo, hi;
            asm("mov.b64 {%0, %1}, %2;" : "=f"(lo), "=f"(hi) : "l"(acc[i][jp]));
            lo += bs[col0 + 2 * jp];
            hi += bs[col0 + 2 * jp + 1];
            lo = (lo > 0.f) ? lo : 0.01f * lo;
            hi = (hi > 0.f) ? hi : 0.01f * hi;
            vrow[r * VP + col0 + 2 * jp] = lo;
            vrow[r * VP + col0 + 2 * jp + 1] = hi;
        }
    }
    __syncthreads();

    if (tid < nrows) {
        const float* vr = &vrow[tid * VP];
        float logits[10];
#pragma unroll
        for (int j = 0; j < 10; j++) logits[j] = bl_s[j];
#pragma unroll
        for (int k = 0; k < DOUT; k++) {
            float v = vr[k];
#pragma unroll
            for (int j = 0; j < 10; j++)
                logits[j] = fmaf(v, Wl_s[k * 10 + j], logits[j]);
        }
        float mx = logits[0];
#pragma unroll
        for (int j = 1; j < 10; j++) mx = fmaxf(mx, logits[j]);
        float s = 0.f;
#pragma unroll
        for (int j = 0; j < 10; j++) s += __expf(logits[j] - mx);
        float lse = mx + __logf(s);
        float* outr = out + (size_t)(row0 + tid) * 10;
#pragma unroll
        for (int j = 0; j < 10; j++) outr[j] = logits[j] - lse;
    }
}

// ---------------------------------------------------------------------------
// launch
// ---------------------------------------------------------------------------
extern "C" void kernel_launch(void* const* d_in, const int* in_sizes, int n_in,
                              void* d_out, int out_size) {
    const float* x = (const float*)d_in[0];
    const int* edge = (const int*)d_in[1];  // int32 (JAX downcast)
    const float* W1 = (const float*)d_in[2];
    const float* b1 = (const float*)d_in[3];
    const float* W2 = (const float*)d_in[4];
    const float* b2 = (const float*)d_in[5];
    const float* W3 = (const float*)d_in[6];
    const float* b3 = (const float*)d_in[7];
    const float* Wl = (const float*)d_in[8];
    const float* bl = (const float*)d_in[9];
    float* out = (float*)d_out;

    const int n = in_sizes[0] / 64;  // 100000
    const int E = in_sizes[1] / 2;   // 1000000
    const int* src = edge;
    const int* dst = edge + E;

    float *bufA, *bufB, *bufC, *dinv;
    int *cur, *csrc;
    __half *hX, *hM, *hA2;
    cudaGetSymbolAddress((void**)&bufA, g_bufA);
    cudaGetSymbolAddress((void**)&bufB, g_bufB);
    cudaGetSymbolAddress((void**)&bufC, g_bufC);
    cudaGetSymbolAddress((void**)&dinv, g_dinv);
    cudaGetSymbolAddress((void**)&cur, g_cur);
    cudaGetSymbolAddress((void**)&csrc, g_csrc);
    cudaGetSymbolAddress((void**)&hX, g_hX);
    cudaGetSymbolAddress((void**)&hM, g_hM);
    cudaGetSymbolAddress((void**)&hA2, g_hA2);

    const int T = 256;

    // ---- kernel 1: cursor init + x->fp16 (fused; no dependency sync) ----
    pdl_launch(init_convert, cdiv(n * 16, T), T,
               (const float4*)x, (uint2*)hX, cur, n);

    // ---- bucket CSR scatter + dinv ----
    pdl_launch(csr_scatter, cdiv(E, T), T,
               (const int*)src, (const int*)dst, cur, csrc, E);
    pdl_launch(dinv_fin, cdiv(n, T), T, (const int*)cur, dinv, n);

    // ---- layer 1: fp16 aggregate-first (16 thr/node), GEMM 64->80 ----
    pdl_launch(agg_pre1_h, cdiv(n * 16, T), T,
               (const uint2*)hX, (const int*)cur, (const int*)csrc,
               (const float*)dinv, (float4*)bufB, n);
    pdl_launch(gemm_fused<64, 80, 128, 32, 4, 10, 256, false, false, false>,
               cdiv(n, 128), 256,
               (const float*)bufB, W1, b1, (const float*)dinv,
               (void*)bufA, bufC, n);

    // ---- layer 2: GEMM 80->40 (fp16 messages), aggregate-after -> A2 fp16 --
    pdl_launch(gemm_fused<80, 40, 256, 20, 4, 10, 256, true, true, true>,
               cdiv(n, 256), 256,
               (const float*)bufC, W2, b2, (const float*)dinv,
               (void*)hM, bufA, n);
    pdl_launch(agg2_h, cdiv(n * 10, T), T,
               (const uint2*)hM, (const int*)cur, (const int*)csrc,
               (const float*)dinv, (const float4*)bufA, (uint2*)hA2, n);

    // ---- layer 3: fp16 aggregate-first (10 thr/node, leaky fused) ----
    pdl_launch(agg3_h, cdiv(n * 10, T), T,
               (const uint2*)hA2, (const int*)cur, (const int*)csrc,
               (const float*)dinv, (float4*)bufB, n);

    // ---- gemm3 (40->50) fused with classifier head + log_softmax ----
    pdl_launch(gemm3_head, cdiv(n, 128), 160,
               (const float*)bufB, W3, b3, Wl, bl, out, n);
}